// round 9
// baseline (speedup 1.0000x reference)
#include <cuda_runtime.h>
#include <cuda_bf16.h>
#include <cstdint>

#define MDIM  128
#define FEAT  8256          // MDIM*(MDIM+1)/2
#define HID   1651
#define NP    1664          // HID padded to 13*128
#define KP    8320          // FEAT padded to 130*64
#define BATCH 4096
#define KST   130           // KP / 64 (64 bf16 elems = 128B per stage-row)
#define ROWB  (KP * 2)      // row pitch in bytes

#define A_BYTES     16384   // 128 rows x 128B
#define B_BYTES     16384   // 128 rows x 128B
#define STAGE_BYTES (A_BYTES + B_BYTES)   // 32 KB
#define NSTAGE      4
#define SMEM_TOTAL  (NSTAGE * STAGE_BYTES)   // 128 KB

#define MT 32               // M tiles (4096/128)
#define NT 13               // N tiles (1664/128)
#define NTILES (MT*NT)      // 416
#define GRID   148          // persistent, 1 CTA/SM

// ---------------- device scratch ----------------
__device__ __nv_bfloat16 g_xb [(size_t)BATCH * KP];   // 68.2 MB
__device__ __nv_bfloat16 g_w1b[(size_t)NP    * KP];   // 27.7 MB
__device__ float g_b1[NP];
__device__ float g_w2[NP];
__device__ float g_logits[BATCH];

// ---------------- helpers ----------------
__device__ __forceinline__ uint32_t smem_u32(const void* p) {
    uint32_t a;
    asm("{ .reg .u64 t; cvta.to.shared.u64 t, %1; cvt.u32.u64 %0, t; }" : "=r"(a) : "l"(p));
    return a;
}
#define SWZ128(off) ((off) ^ (((off) >> 3) & 0x70))

__device__ __forceinline__ void ldsm_x4(uint32_t& r0, uint32_t& r1, uint32_t& r2, uint32_t& r3,
                                        uint32_t addr) {
    asm volatile("ldmatrix.sync.aligned.m8n8.x4.shared.b16 {%0,%1,%2,%3}, [%4];"
                 : "=r"(r0), "=r"(r1), "=r"(r2), "=r"(r3) : "r"(addr));
}
__device__ __forceinline__ void mma_bf16(float* c, const uint32_t* a, const uint32_t* b) {
    asm volatile(
        "mma.sync.aligned.m16n8k16.row.col.f32.bf16.bf16.f32 "
        "{%0,%1,%2,%3}, {%4,%5,%6,%7}, {%8,%9}, {%0,%1,%2,%3};"
        : "+f"(c[0]), "+f"(c[1]), "+f"(c[2]), "+f"(c[3])
        : "r"(a[0]), "r"(a[1]), "r"(a[2]), "r"(a[3]), "r"(b[0]), "r"(b[1]));
}

// ---------------- prep kernels ----------------
__global__ void prep_small(const float* __restrict__ b1, const float* __restrict__ w2) {
    int i = blockIdx.x * blockDim.x + threadIdx.x;
    if (i < NP) {
        g_b1[i] = (i < HID) ? b1[i] : 0.0f;
        g_w2[i] = (i < HID) ? w2[i] : 0.0f;
    }
    if (i < BATCH) g_logits[i] = 0.0f;
}

// W1 fp32 -> bf16; pad rows [HID,NP) and cols [FEAT,KP) zero. 4 elems/thread.
__global__ void prep_w1b(const float* __restrict__ W1) {
    int n  = blockIdx.y;
    int k4 = blockIdx.x * blockDim.x + threadIdx.x;
    if (k4 >= KP / 4) return;
    __nv_bfloat16 o[4] = {__float2bfloat16(0.f), __float2bfloat16(0.f),
                          __float2bfloat16(0.f), __float2bfloat16(0.f)};
    if (n < HID) {
        int k = k4 * 4;
        if (k + 3 < FEAT) {
            float4 v = *(const float4*)&W1[(size_t)n * FEAT + k];
            o[0] = __float2bfloat16(v.x); o[1] = __float2bfloat16(v.y);
            o[2] = __float2bfloat16(v.z); o[3] = __float2bfloat16(v.w);
        } else {
#pragma unroll
            for (int j = 0; j < 4; j++)
                if (k + j < FEAT) o[j] = __float2bfloat16(W1[(size_t)n * FEAT + k + j]);
        }
    }
    *(uint2*)&g_w1b[(size_t)n * KP + k4 * 4] = *(uint2*)o;
}

// triu extraction + bf16 convert, float4 loads, lower-triangle groups skipped
__global__ __launch_bounds__(256) void triub(const float* __restrict__ sim) {
    int b   = blockIdx.x;
    int tid = threadIdx.x;
    const float* base = sim + (size_t)b * MDIM * MDIM;
    __nv_bfloat16* out = g_xb + (size_t)b * KP;
#pragma unroll
    for (int it = 0; it < 16; ++it) {
        int idx = tid + it * 256;       // 0..4095: (row, group-of-4)
        int i = idx >> 5;
        int g = idx & 31;
        int j0 = g * 4;
        if (j0 + 3 >= i) {
            float4 v = *(const float4*)&base[i * MDIM + j0];
            int rowoff = i * MDIM - (i * (i - 1)) / 2 - i;   // out index = rowoff + j
            float vv[4] = {v.x, v.y, v.z, v.w};
#pragma unroll
            for (int l = 0; l < 4; l++) {
                int j = j0 + l;
                if (j >= i) out[rowoff + j] = __float2bfloat16(vv[l]);
            }
        }
    }
    if (tid < KP - FEAT) out[FEAT + tid] = __float2bfloat16(0.f);
}

// ---------------- bf16 GEMM: persistent, CTA 128x128, 16 warps (32x32), 1 CTA/SM ----------------
__global__ __launch_bounds__(512, 1) void gemm_bf16() {
    extern __shared__ __align__(1024) uint8_t smem[];
    const uint32_t sbase = smem_u32(smem);
    const int tid = threadIdx.x;
    const int wid = tid >> 5;
    const int lid = tid & 31;
    const int wm  = wid & 3;            // M quarter (32 rows)
    const int wn  = wid >> 2;           // N quarter (32 cols)

    // ---- hoisted ldmatrix addressing (row-invariant swizzle XOR; byte-identical to fp8 k32) ----
    const int aRow0 = wm * 32 + ((lid >> 3) & 1) * 8 + (lid & 7);   // +16 per mi (row&7 invariant)
    const int aCol  = (lid >> 4) * 16;
    const uint32_t aXor = (uint32_t)((aRow0 & 7) << 4);
    const int bRow0 = wn * 32 + (lid >> 4) * 8 + (lid & 7);         // +16 per p
    const int bCol  = ((lid >> 3) & 1) * 16;
    const uint32_t bXor = (uint32_t)((bRow0 & 7) << 4);

    uint32_t aOff[4], bOff[4];   // per k16-step (32-byte column step)
#pragma unroll
    for (int ks = 0; ks < 4; ks++) {
        aOff[ks] = (uint32_t)(aRow0 * 128) + (((uint32_t)(aCol + ks * 32)) ^ aXor);
        bOff[ks] = A_BYTES + (uint32_t)(bRow0 * 128) + (((uint32_t)(bCol + ks * 32)) ^ bXor);
    }

    for (int t = blockIdx.x; t < NTILES; t += GRID) {
        const int m0 = (t / NT) * 128;
        const int n0 = (t % NT) * 128;

        float acc[2][4][4];
#pragma unroll
        for (int mi = 0; mi < 2; mi++)
#pragma unroll
            for (int ni = 0; ni < 4; ni++)
#pragma unroll
                for (int c = 0; c < 4; c++) acc[mi][ni][c] = 0.0f;

        auto load_stage = [&](int buf, int kByte) {
            uint32_t st = sbase + buf * STAGE_BYTES;
            // A: 1024 chunks (128 rows x 8), B: 1024 chunks; 4/thread
#pragma unroll
            for (int it = 0; it < 4; ++it) {
                int idx = tid + it * 512;           // 0..2047
                bool isB = idx >= 1024;
                int rel  = idx & 1023;
                int r    = rel >> 3;
                int c    = rel & 7;
                const uint8_t* src = isB
                    ? (const uint8_t*)g_w1b + (size_t)(n0 + r) * ROWB + kByte + c * 16
                    : (const uint8_t*)g_xb  + (size_t)(m0 + r) * ROWB + kByte + c * 16;
                uint32_t dst = st + (isB ? A_BYTES : 0) + SWZ128((uint32_t)(r * 128 + c * 16));
                asm volatile("cp.async.cg.shared.global [%0], [%1], 16;"
                             :: "r"(dst), "l"(src) : "memory");
            }
            asm volatile("cp.async.commit_group;" ::: "memory");
        };

        load_stage(0, 0);
        load_stage(1, 128);
        load_stage(2, 256);

        for (int s = 0; s < KST; ++s) {
            asm volatile("cp.async.wait_group 2;" ::: "memory");
            __syncthreads();

            if (s + 3 < KST) load_stage((s + 3) & 3, (s + 3) * 128);
            else             asm volatile("cp.async.commit_group;" ::: "memory");

            const uint32_t stg = sbase + (s & 3) * STAGE_BYTES;

#pragma unroll
            for (int ks = 0; ks < 4; ++ks) {
                uint32_t b[4][2];
#pragma unroll
                for (int p = 0; p < 2; p++) {
                    uint32_t r0, r1, r2, r3;
                    ldsm_x4(r0, r1, r2, r3, stg + bOff[ks] + p * 2048);
                    b[2 * p][0] = r0; b[2 * p][1] = r1;
                    b[2 * p + 1][0] = r2; b[2 * p + 1][1] = r3;
                }
                uint32_t a[2][4];
                ldsm_x4(a[0][0], a[0][1], a[0][2], a[0][3], stg + aOff[ks]);
                ldsm_x4(a[1][0], a[1][1], a[1][2], a[1][3], stg + aOff[ks] + 2048);
#pragma unroll
                for (int mi = 0; mi < 2; mi++)
#pragma unroll
                    for (int ni = 0; ni < 4; ni++)
                        mma_bf16(acc[mi][ni], a[mi], b[ni]);
            }
        }
        __syncthreads();   // drain smem reads before next tile's prologue overwrites

        // -------- fused epilogue: logits[m] += sum_n relu(acc + b1) * w2 --------
        const int qrow = lid >> 2;
        const int qcol = lid & 3;
#pragma unroll
        for (int mi = 0; mi < 2; mi++) {
            float r0 = 0.f, r1 = 0.f;
#pragma unroll
            for (int ni = 0; ni < 4; ni++) {
                int n = n0 + wn * 32 + ni * 8 + qcol * 2;
                float b1a = g_b1[n],     w2a = g_w2[n];
                float b1b = g_b1[n + 1], w2b = g_w2[n + 1];
                r0 += fmaxf(acc[mi][ni][0] + b1a, 0.f) * w2a
                    + fmaxf(acc[mi][ni][1] + b1b, 0.f) * w2b;
                r1 += fmaxf(acc[mi][ni][2] + b1a, 0.f) * w2a
                    + fmaxf(acc[mi][ni][3] + b1b, 0.f) * w2b;
            }
            r0 += __shfl_xor_sync(0xffffffffu, r0, 1);
            r0 += __shfl_xor_sync(0xffffffffu, r0, 2);
            r1 += __shfl_xor_sync(0xffffffffu, r1, 1);
            r1 += __shfl_xor_sync(0xffffffffu, r1, 2);
            if (qcol == 0) {
                int row = m0 + wm * 32 + mi * 16 + qrow;
                atomicAdd(&g_logits[row],     r0);
                atomicAdd(&g_logits[row + 8], r1);
            }
        }
    }
}

// ---------------- finalize ----------------
__global__ void finalize(const float* __restrict__ b2, float* __restrict__ out) {
    int i = blockIdx.x * blockDim.x + threadIdx.x;
    if (i < BATCH) {
        float z = g_logits[i] + b2[0];
        out[i] = 1.0f / (1.0f + expf(-z));
    }
}

// ---------------- launch ----------------
extern "C" void kernel_launch(void* const* d_in, const int* in_sizes, int n_in,
                              void* d_out, int out_size) {
    const float* sim = (const float*)d_in[0];
    const float* W1  = (const float*)d_in[1];
    const float* b1  = (const float*)d_in[2];
    const float* W2  = (const float*)d_in[3];
    const float* b2  = (const float*)d_in[4];
    float* out = (float*)d_out;

    cudaFuncSetAttribute(gemm_bf16, cudaFuncAttributeMaxDynamicSharedMemorySize, SMEM_TOTAL);

    prep_small<<<(BATCH + 255) / 256, 256>>>(b1, W2);
    prep_w1b<<<dim3((KP / 4 + 255) / 256, NP), 256>>>(W1);
    triub<<<BATCH, 256>>>(sim);
    gemm_bf16<<<GRID, 512, SMEM_TOTAL>>>();
    finalize<<<(BATCH + 255) / 256, 256>>>(b2, out);
}

// round 10
// speedup vs baseline: 1.0376x; 1.0376x over previous
#include <cuda_runtime.h>
#include <cuda_bf16.h>
#include <cstdint>

#define MDIM  128
#define FEAT  8256          // MDIM*(MDIM+1)/2
#define HID   1651
#define NP    1664          // HID padded to 13*128
#define KP    8320          // FEAT padded to 65*128
#define BATCH 4096
#define KST   65            // KP / 128 (128 bf16 = 256B per stage-row)
#define ROWB  (KP * 2)      // global row pitch in bytes

// stage layout: [A0 16K | A1 16K | B0 16K | B1 16K]  (atom = 128 rows x 128B)
#define ATOM_BYTES  16384
#define B_BASE      32768
#define STAGE_BYTES 65536
#define NSTAGE      3
#define SMEM_TOTAL  (NSTAGE * STAGE_BYTES)   // 192 KB

#define MT 32               // M tiles (4096/128)
#define NT 13               // N tiles (1664/128)
#define NTILES (MT*NT)      // 416
#define GRID   148          // persistent, 1 CTA/SM

// ---------------- device scratch ----------------
__device__ __nv_bfloat16 g_xb [(size_t)BATCH * KP];   // 68.2 MB
__device__ __nv_bfloat16 g_w1b[(size_t)NP    * KP];   // 27.7 MB
__device__ float g_b1[NP];
__device__ float g_w2[NP];
__device__ float g_logits[BATCH];

// ---------------- helpers ----------------
__device__ __forceinline__ uint32_t smem_u32(const void* p) {
    uint32_t a;
    asm("{ .reg .u64 t; cvta.to.shared.u64 t, %1; cvt.u32.u64 %0, t; }" : "=r"(a) : "l"(p));
    return a;
}
#define SWZ128(off) ((off) ^ (((off) >> 3) & 0x70))

__device__ __forceinline__ void ldsm_x4(uint32_t& r0, uint32_t& r1, uint32_t& r2, uint32_t& r3,
                                        uint32_t addr) {
    asm volatile("ldmatrix.sync.aligned.m8n8.x4.shared.b16 {%0,%1,%2,%3}, [%4];"
                 : "=r"(r0), "=r"(r1), "=r"(r2), "=r"(r3) : "r"(addr));
}
__device__ __forceinline__ void mma_bf16(float* c, const uint32_t* a, const uint32_t* b) {
    asm volatile(
        "mma.sync.aligned.m16n8k16.row.col.f32.bf16.bf16.f32 "
        "{%0,%1,%2,%3}, {%4,%5,%6,%7}, {%8,%9}, {%0,%1,%2,%3};"
        : "+f"(c[0]), "+f"(c[1]), "+f"(c[2]), "+f"(c[3])
        : "r"(a[0]), "r"(a[1]), "r"(a[2]), "r"(a[3]), "r"(b[0]), "r"(b[1]));
}

// ---------------- prep kernels ----------------
__global__ void prep_small(const float* __restrict__ b1, const float* __restrict__ w2) {
    int i = blockIdx.x * blockDim.x + threadIdx.x;
    if (i < NP) {
        g_b1[i] = (i < HID) ? b1[i] : 0.0f;
        g_w2[i] = (i < HID) ? w2[i] : 0.0f;
    }
    if (i < BATCH) g_logits[i] = 0.0f;
}

// W1 fp32 -> bf16; pad rows [HID,NP) and cols [FEAT,KP) zero
__global__ void prep_w1b(const float* __restrict__ W1) {
    int n  = blockIdx.y;
    int k4 = blockIdx.x * blockDim.x + threadIdx.x;
    if (k4 >= KP / 4) return;
    __nv_bfloat16 o[4] = {__float2bfloat16(0.f), __float2bfloat16(0.f),
                          __float2bfloat16(0.f), __float2bfloat16(0.f)};
    if (n < HID) {
        int k = k4 * 4;
        if (k + 3 < FEAT) {
            float4 v = *(const float4*)&W1[(size_t)n * FEAT + k];
            o[0] = __float2bfloat16(v.x); o[1] = __float2bfloat16(v.y);
            o[2] = __float2bfloat16(v.z); o[3] = __float2bfloat16(v.w);
        } else {
#pragma unroll
            for (int j = 0; j < 4; j++)
                if (k + j < FEAT) o[j] = __float2bfloat16(W1[(size_t)n * FEAT + k + j]);
        }
    }
    *(uint2*)&g_w1b[(size_t)n * KP + k4 * 4] = *(uint2*)o;
}

// triu extraction + bf16 convert
__global__ __launch_bounds__(256) void triub(const float* __restrict__ sim) {
    int b   = blockIdx.x;
    int tid = threadIdx.x;
    const float* base = sim + (size_t)b * MDIM * MDIM;
    __nv_bfloat16* out = g_xb + (size_t)b * KP;
#pragma unroll
    for (int it = 0; it < 16; ++it) {
        int idx = tid + it * 256;       // 0..4095: (row, group-of-4)
        int i = idx >> 5;
        int g = idx & 31;
        int j0 = g * 4;
        if (j0 + 3 >= i) {
            float4 v = *(const float4*)&base[i * MDIM + j0];
            int rowoff = i * MDIM - (i * (i - 1)) / 2 - i;
            float vv[4] = {v.x, v.y, v.z, v.w};
#pragma unroll
            for (int l = 0; l < 4; l++) {
                int j = j0 + l;
                if (j >= i) out[rowoff + j] = __float2bfloat16(vv[l]);
            }
        }
    }
    if (tid < KP - FEAT) out[FEAT + tid] = __float2bfloat16(0.f);
}

// ---------------- bf16 GEMM: CTA 128x128, 16 warps (32x32), k128 stages, frag double-buffer ----------------
__global__ __launch_bounds__(512, 1) void gemm_bf16() {
    extern __shared__ __align__(1024) uint8_t smem[];
    const uint32_t sbase = smem_u32(smem);
    const int tid = threadIdx.x;
    const int wid = tid >> 5;
    const int lid = tid & 31;
    const int wm  = wid & 3;            // M quarter (32 rows)
    const int wn  = wid >> 2;           // N quarter (32 cols)

    // hoisted ldmatrix addressing (row-invariant swizzle XOR)
    const int aRow0 = wm * 32 + ((lid >> 3) & 1) * 8 + (lid & 7);
    const int aCol  = (lid >> 4) * 16;
    const uint32_t aXor = (uint32_t)((aRow0 & 7) << 4);
    const int bRow0 = wn * 32 + (lid >> 4) * 8 + (lid & 7);
    const int bCol  = ((lid >> 3) & 1) * 16;
    const uint32_t bXor = (uint32_t)((bRow0 & 7) << 4);

    // 8 k16-steps per stage: ks&3 selects 32B column, ks>>2 selects atom (+16KB)
    uint32_t aOff[8], bOff[8];
#pragma unroll
    for (int ks = 0; ks < 8; ks++) {
        uint32_t hw = (ks >> 2) * ATOM_BYTES;
        aOff[ks] = hw + (uint32_t)(aRow0 * 128) + (((uint32_t)(aCol + (ks & 3) * 32)) ^ aXor);
        bOff[ks] = B_BASE + hw + (uint32_t)(bRow0 * 128) + (((uint32_t)(bCol + (ks & 3) * 32)) ^ bXor);
    }

    for (int t = blockIdx.x; t < NTILES; t += GRID) {
        const int m0 = (t / NT) * 128;
        const int n0 = (t % NT) * 128;

        float acc[2][4][4];
#pragma unroll
        for (int mi = 0; mi < 2; mi++)
#pragma unroll
            for (int ni = 0; ni < 4; ni++)
#pragma unroll
                for (int c = 0; c < 4; c++) acc[mi][ni][c] = 0.0f;

        auto load_stage = [&](int buf, int kByte) {
            uint32_t st = sbase + buf * STAGE_BYTES;
            // A: 2048 chunks (2 atoms x 128 rows x 8), B: 2048; 8/thread
#pragma unroll
            for (int it = 0; it < 8; ++it) {
                int idx = tid + it * 512;           // 0..4095
                bool isB = idx >= 2048;
                int rel  = idx & 2047;
                int h    = rel >> 10;               // atom
                int r    = (rel >> 3) & 127;
                int c    = rel & 7;
                const uint8_t* src = isB
                    ? (const uint8_t*)g_w1b + (size_t)(n0 + r) * ROWB + kByte + h * 128 + c * 16
                    : (const uint8_t*)g_xb  + (size_t)(m0 + r) * ROWB + kByte + h * 128 + c * 16;
                uint32_t dst = st + (isB ? B_BASE : 0) + h * ATOM_BYTES
                             + SWZ128((uint32_t)(r * 128 + c * 16));
                asm volatile("cp.async.cg.shared.global [%0], [%1], 16;"
                             :: "r"(dst), "l"(src) : "memory");
            }
            asm volatile("cp.async.commit_group;" ::: "memory");
        };

        load_stage(0, 0);
        load_stage(1, 256);

        for (int s = 0; s < KST; ++s) {
            asm volatile("cp.async.wait_group 1;" ::: "memory");
            __syncthreads();

            if (s + 2 < KST) load_stage((s + 2) % NSTAGE, (s + 2) * 256);
            else             asm volatile("cp.async.commit_group;" ::: "memory");

            const uint32_t stg = sbase + (s % NSTAGE) * STAGE_BYTES;

            // fragment double-buffer across 8 k16-steps
            uint32_t a[2][2][4], b[2][4][2];
            {
                ldsm_x4(a[0][0][0], a[0][0][1], a[0][0][2], a[0][0][3], stg + aOff[0]);
                ldsm_x4(a[0][1][0], a[0][1][1], a[0][1][2], a[0][1][3], stg + aOff[0] + 2048);
                uint32_t r0, r1, r2, r3;
                ldsm_x4(r0, r1, r2, r3, stg + bOff[0]);
                b[0][0][0] = r0; b[0][0][1] = r1; b[0][1][0] = r2; b[0][1][1] = r3;
                ldsm_x4(r0, r1, r2, r3, stg + bOff[0] + 2048);
                b[0][2][0] = r0; b[0][2][1] = r1; b[0][3][0] = r2; b[0][3][1] = r3;
            }
#pragma unroll
            for (int ks = 0; ks < 8; ++ks) {
                const int cur = ks & 1, nxt = cur ^ 1;
                if (ks < 7) {
                    ldsm_x4(a[nxt][0][0], a[nxt][0][1], a[nxt][0][2], a[nxt][0][3],
                            stg + aOff[ks + 1]);
                    ldsm_x4(a[nxt][1][0], a[nxt][1][1], a[nxt][1][2], a[nxt][1][3],
                            stg + aOff[ks + 1] + 2048);
                    uint32_t r0, r1, r2, r3;
                    ldsm_x4(r0, r1, r2, r3, stg + bOff[ks + 1]);
                    b[nxt][0][0] = r0; b[nxt][0][1] = r1; b[nxt][1][0] = r2; b[nxt][1][1] = r3;
                    ldsm_x4(r0, r1, r2, r3, stg + bOff[ks + 1] + 2048);
                    b[nxt][2][0] = r0; b[nxt][2][1] = r1; b[nxt][3][0] = r2; b[nxt][3][1] = r3;
                }
#pragma unroll
                for (int mi = 0; mi < 2; mi++)
#pragma unroll
                    for (int ni = 0; ni < 4; ni++)
                        mma_bf16(acc[mi][ni], a[cur][mi], b[cur][ni]);
            }
        }
        __syncthreads();   // drain smem reads before next tile's prologue overwrites

        // -------- fused epilogue: logits[m] += sum_n relu(acc + b1) * w2 --------
        const int qrow = lid >> 2;
        const int qcol = lid & 3;
#pragma unroll
        for (int mi = 0; mi < 2; mi++) {
            float r0 = 0.f, r1 = 0.f;
#pragma unroll
            for (int ni = 0; ni < 4; ni++) {
                int n = n0 + wn * 32 + ni * 8 + qcol * 2;
                float b1a = g_b1[n],     w2a = g_w2[n];
                float b1b = g_b1[n + 1], w2b = g_w2[n + 1];
                r0 += fmaxf(acc[mi][ni][0] + b1a, 0.f) * w2a
                    + fmaxf(acc[mi][ni][1] + b1b, 0.f) * w2b;
                r1 += fmaxf(acc[mi][ni][2] + b1a, 0.f) * w2a
                    + fmaxf(acc[mi][ni][3] + b1b, 0.f) * w2b;
            }
            r0 += __shfl_xor_sync(0xffffffffu, r0, 1);
            r0 += __shfl_xor_sync(0xffffffffu, r0, 2);
            r1 += __shfl_xor_sync(0xffffffffu, r1, 1);
            r1 += __shfl_xor_sync(0xffffffffu, r1, 2);
            if (qcol == 0) {
                int row = m0 + wm * 32 + mi * 16 + qrow;
                atomicAdd(&g_logits[row],     r0);
                atomicAdd(&g_logits[row + 8], r1);
            }
        }
    }
}

// ---------------- finalize ----------------
__global__ void finalize(const float* __restrict__ b2, float* __restrict__ out) {
    int i = blockIdx.x * blockDim.x + threadIdx.x;
    if (i < BATCH) {
        float z = g_logits[i] + b2[0];
        out[i] = 1.0f / (1.0f + expf(-z));
    }
}

// ---------------- launch ----------------
extern "C" void kernel_launch(void* const* d_in, const int* in_sizes, int n_in,
                              void* d_out, int out_size) {
    const float* sim = (const float*)d_in[0];
    const float* W1  = (const float*)d_in[1];
    const float* b1  = (const float*)d_in[2];
    const float* W2  = (const float*)d_in[3];
    const float* b2  = (const float*)d_in[4];
    float* out = (float*)d_out;

    cudaFuncSetAttribute(gemm_bf16, cudaFuncAttributeMaxDynamicSharedMemorySize, SMEM_TOTAL);

    prep_small<<<(BATCH + 255) / 256, 256>>>(b1, W2);
    prep_w1b<<<dim3((KP / 4 + 255) / 256, NP), 256>>>(W1);
    triub<<<BATCH, 256>>>(sim);
    gemm_bf16<<<GRID, 512, SMEM_TOTAL>>>();
    finalize<<<(BATCH + 255) / 256, 256>>>(b2, out);
}

// round 11
// speedup vs baseline: 1.1220x; 1.0814x over previous
#include <cuda_runtime.h>
#include <cuda_bf16.h>
#include <cstdint>

#define MDIM  128
#define FEAT  8256          // MDIM*(MDIM+1)/2
#define HID   1651
#define NP    1664          // HID padded to 13*128
#define KP    8320          // FEAT padded to 130*64
#define BATCH 4096
#define ROWB  (KP * 2)      // global row pitch in bytes

// stage = K64 slice: [A 128rows x 128B | B 128rows x 128B] = 32KB
// pair  = 2 stages (even for group0, odd for group1) = 64KB
#define STG_A       16384
#define STG_BYTES   32768
#define PAIR_BYTES  65536
#define NPAIR       3
#define SMEM_TOTAL  (NPAIR * PAIR_BYTES)   // 192 KB
#define KPAIRS      65                      // KP / 128

#define MT 32
#define NT 13
#define NTILES (MT*NT)      // 416
#define GRID   148

#define HSTR 132            // merge-buffer row stride (floats)

// ---------------- device scratch ----------------
__device__ __nv_bfloat16 g_xb [(size_t)BATCH * KP];   // 68.2 MB
__device__ __nv_bfloat16 g_w1b[(size_t)NP    * KP];   // 27.7 MB
__device__ float g_b1[NP];
__device__ float g_w2[NP];
__device__ float g_logits[BATCH];

// ---------------- helpers ----------------
__device__ __forceinline__ uint32_t smem_u32(const void* p) {
    uint32_t a;
    asm("{ .reg .u64 t; cvta.to.shared.u64 t, %1; cvt.u32.u64 %0, t; }" : "=r"(a) : "l"(p));
    return a;
}
#define SWZ128(off) ((off) ^ (((off) >> 3) & 0x70))

__device__ __forceinline__ void ldsm_x4(uint32_t& r0, uint32_t& r1, uint32_t& r2, uint32_t& r3,
                                        uint32_t addr) {
    asm volatile("ldmatrix.sync.aligned.m8n8.x4.shared.b16 {%0,%1,%2,%3}, [%4];"
                 : "=r"(r0), "=r"(r1), "=r"(r2), "=r"(r3) : "r"(addr));
}
__device__ __forceinline__ void mma_bf16(float* c, const uint32_t* a, const uint32_t* b) {
    asm volatile(
        "mma.sync.aligned.m16n8k16.row.col.f32.bf16.bf16.f32 "
        "{%0,%1,%2,%3}, {%4,%5,%6,%7}, {%8,%9}, {%0,%1,%2,%3};"
        : "+f"(c[0]), "+f"(c[1]), "+f"(c[2]), "+f"(c[3])
        : "r"(a[0]), "r"(a[1]), "r"(a[2]), "r"(a[3]), "r"(b[0]), "r"(b[1]));
}

// ---------------- prep kernels ----------------
__global__ void prep_small(const float* __restrict__ b1, const float* __restrict__ w2) {
    int i = blockIdx.x * blockDim.x + threadIdx.x;
    if (i < NP) {
        g_b1[i] = (i < HID) ? b1[i] : 0.0f;
        g_w2[i] = (i < HID) ? w2[i] : 0.0f;
    }
    if (i < BATCH) g_logits[i] = 0.0f;
}

__global__ void prep_w1b(const float* __restrict__ W1) {
    int n  = blockIdx.y;
    int k4 = blockIdx.x * blockDim.x + threadIdx.x;
    if (k4 >= KP / 4) return;
    __nv_bfloat16 o[4] = {__float2bfloat16(0.f), __float2bfloat16(0.f),
                          __float2bfloat16(0.f), __float2bfloat16(0.f)};
    if (n < HID) {
        int k = k4 * 4;
        if (k + 3 < FEAT) {
            float4 v = *(const float4*)&W1[(size_t)n * FEAT + k];
            o[0] = __float2bfloat16(v.x); o[1] = __float2bfloat16(v.y);
            o[2] = __float2bfloat16(v.z); o[3] = __float2bfloat16(v.w);
        } else {
#pragma unroll
            for (int j = 0; j < 4; j++)
                if (k + j < FEAT) o[j] = __float2bfloat16(W1[(size_t)n * FEAT + k + j]);
        }
    }
    *(uint2*)&g_w1b[(size_t)n * KP + k4 * 4] = *(uint2*)o;
}

__global__ __launch_bounds__(256) void triub(const float* __restrict__ sim) {
    int b   = blockIdx.x;
    int tid = threadIdx.x;
    const float* base = sim + (size_t)b * MDIM * MDIM;
    __nv_bfloat16* out = g_xb + (size_t)b * KP;
#pragma unroll
    for (int it = 0; it < 16; ++it) {
        int idx = tid + it * 256;
        int i = idx >> 5;
        int g = idx & 31;
        int j0 = g * 4;
        if (j0 + 3 >= i) {
            float4 v = *(const float4*)&base[i * MDIM + j0];
            int rowoff = i * MDIM - (i * (i - 1)) / 2 - i;
            float vv[4] = {v.x, v.y, v.z, v.w};
#pragma unroll
            for (int l = 0; l < 4; l++) {
                int j = j0 + l;
                if (j >= i) out[rowoff + j] = __float2bfloat16(vv[l]);
            }
        }
    }
    if (tid < KP - FEAT) out[FEAT + tid] = __float2bfloat16(0.f);
}

// ---------------- bf16 GEMM: CTA 128x128, 16 warps = 2 K-groups x 8 warps (32x64) ----------------
__global__ __launch_bounds__(512, 1) void gemm_bf16() {
    extern __shared__ __align__(1024) uint8_t smem[];
    const uint32_t sbase = smem_u32(smem);
    const int tid = threadIdx.x;
    const int wid = tid >> 5;
    const int lid = tid & 31;
    const int grp = wid >> 3;           // K-split group (0: even stages, 1: odd)
    const int w8  = wid & 7;
    const int wm  = w8 & 3;             // 4 x 32 rows
    const int wn  = w8 >> 2;            // 2 x 64 cols

    // hoisted ldmatrix addressing (row-invariant swizzle XOR)
    const int aRow0 = wm * 32 + ((lid >> 3) & 1) * 8 + (lid & 7);   // +16 per mi
    const int aCol  = (lid >> 4) * 16;
    const uint32_t aXor = (uint32_t)((aRow0 & 7) << 4);
    const int bRow0 = wn * 64 + (lid >> 4) * 8 + (lid & 7);         // +16 per p
    const int bCol  = ((lid >> 3) & 1) * 16;
    const uint32_t bXor = (uint32_t)((bRow0 & 7) << 4);

    uint32_t aOff[4], bOff[4];
#pragma unroll
    for (int ks = 0; ks < 4; ks++) {
        aOff[ks] = (uint32_t)(aRow0 * 128) + (((uint32_t)(aCol + ks * 32)) ^ aXor);
        bOff[ks] = STG_A + (uint32_t)(bRow0 * 128) + (((uint32_t)(bCol + ks * 32)) ^ bXor);
    }

    const int qrow = lid >> 2;
    const int qcol = lid & 3;
    float* sh = (float*)smem;           // merge buffer (reused pair smem)

    for (int t = blockIdx.x; t < NTILES; t += GRID) {
        const int m0 = (t / NT) * 128;
        const int n0 = (t % NT) * 128;

        float acc[2][8][4];
#pragma unroll
        for (int mi = 0; mi < 2; mi++)
#pragma unroll
            for (int ni = 0; ni < 8; ni++)
#pragma unroll
                for (int c = 0; c < 4; c++) acc[mi][ni][c] = 0.0f;

        // load a pair (2 consecutive K64 stages), one commit
        auto load_pair = [&](int pb, int kByte) {
            uint32_t st = sbase + pb * PAIR_BYTES;
#pragma unroll
            for (int it = 0; it < 8; ++it) {
                int idx  = tid + it * 512;          // 0..4095
                int half = idx >> 11;               // stage of pair
                int rel  = idx & 2047;
                bool isB = rel >= 1024;
                int r    = (rel >> 3) & 127;
                int c    = rel & 7;
                int kb   = kByte + half * 128 + c * 16;
                const uint8_t* src = isB
                    ? (const uint8_t*)g_w1b + (size_t)(n0 + r) * ROWB + kb
                    : (const uint8_t*)g_xb  + (size_t)(m0 + r) * ROWB + kb;
                uint32_t dst = st + half * STG_BYTES + (isB ? STG_A : 0)
                             + SWZ128((uint32_t)(r * 128 + c * 16));
                asm volatile("cp.async.cg.shared.global [%0], [%1], 16;"
                             :: "r"(dst), "l"(src) : "memory");
            }
            asm volatile("cp.async.commit_group;" ::: "memory");
        };

        load_pair(0, 0);
        load_pair(1, 256);

        for (int p = 0; p < KPAIRS; ++p) {
            asm volatile("cp.async.wait_group 1;" ::: "memory");
            __syncthreads();

            if (p + 2 < KPAIRS) load_pair((p + 2) % NPAIR, (p + 2) * 256);
            else                asm volatile("cp.async.commit_group;" ::: "memory");

            // this group's stage of the pair
            const uint32_t stg = sbase + (p % NPAIR) * PAIR_BYTES + grp * STG_BYTES;

#pragma unroll
            for (int ks = 0; ks < 4; ++ks) {
                uint32_t b[8][2];
#pragma unroll
                for (int pp = 0; pp < 4; pp++) {
                    uint32_t r0, r1, r2, r3;
                    ldsm_x4(r0, r1, r2, r3, stg + bOff[ks] + pp * 2048);
                    b[2 * pp][0] = r0; b[2 * pp][1] = r1;
                    b[2 * pp + 1][0] = r2; b[2 * pp + 1][1] = r3;
                }
                uint32_t a[2][4];
                ldsm_x4(a[0][0], a[0][1], a[0][2], a[0][3], stg + aOff[ks]);
                ldsm_x4(a[1][0], a[1][1], a[1][2], a[1][3], stg + aOff[ks] + 2048);
#pragma unroll
                for (int mi = 0; mi < 2; mi++)
#pragma unroll
                    for (int ni = 0; ni < 8; ni++)
                        mma_bf16(acc[mi][ni], a[mi], b[ni]);
            }
        }
        __syncthreads();   // all compute done; pair smem now reusable as merge buffer

        // -------- K-split merge: group1 -> smem, group0 adds --------
        if (grp == 1) {
#pragma unroll
            for (int mi = 0; mi < 2; mi++)
#pragma unroll
                for (int ni = 0; ni < 8; ni++) {
                    int r = wm * 32 + mi * 16 + qrow;
                    int cI = wn * 64 + ni * 8 + qcol * 2;
                    *(float2*)&sh[r * HSTR + cI]       = make_float2(acc[mi][ni][0], acc[mi][ni][1]);
                    *(float2*)&sh[(r + 8) * HSTR + cI] = make_float2(acc[mi][ni][2], acc[mi][ni][3]);
                }
        }
        __syncthreads();

        if (grp == 0) {
            // -------- fused epilogue: logits[m] += sum_n relu(acc + b1) * w2 --------
#pragma unroll
            for (int mi = 0; mi < 2; mi++) {
                float r0 = 0.f, r1 = 0.f;
#pragma unroll
                for (int ni = 0; ni < 8; ni++) {
                    int r = wm * 32 + mi * 16 + qrow;
                    int cI = wn * 64 + ni * 8 + qcol * 2;
                    float2 p0 = *(const float2*)&sh[r * HSTR + cI];
                    float2 p1 = *(const float2*)&sh[(r + 8) * HSTR + cI];
                    int n = n0 + cI;
                    float b1a = g_b1[n],     w2a = g_w2[n];
                    float b1b = g_b1[n + 1], w2b = g_w2[n + 1];
                    r0 += fmaxf(acc[mi][ni][0] + p0.x + b1a, 0.f) * w2a
                        + fmaxf(acc[mi][ni][1] + p0.y + b1b, 0.f) * w2b;
                    r1 += fmaxf(acc[mi][ni][2] + p1.x + b1a, 0.f) * w2a
                        + fmaxf(acc[mi][ni][3] + p1.y + b1b, 0.f) * w2b;
                }
                r0 += __shfl_xor_sync(0xffffffffu, r0, 1);
                r0 += __shfl_xor_sync(0xffffffffu, r0, 2);
                r1 += __shfl_xor_sync(0xffffffffu, r1, 1);
                r1 += __shfl_xor_sync(0xffffffffu, r1, 2);
                if (qcol == 0) {
                    int row = m0 + wm * 32 + mi * 16 + qrow;
                    atomicAdd(&g_logits[row],     r0);
                    atomicAdd(&g_logits[row + 8], r1);
                }
            }
        }
        __syncthreads();   // merge buffer free before next tile's prologue
    }
}

// ---------------- finalize ----------------
__global__ void finalize(const float* __restrict__ b2, float* __restrict__ out) {
    int i = blockIdx.x * blockDim.x + threadIdx.x;
    if (i < BATCH) {
        float z = g_logits[i] + b2[0];
        out[i] = 1.0f / (1.0f + expf(-z));
    }
}

// ---------------- launch ----------------
extern "C" void kernel_launch(void* const* d_in, const int* in_sizes, int n_in,
                              void* d_out, int out_size) {
    const float* sim = (const float*)d_in[0];
    const float* W1  = (const float*)d_in[1];
    const float* b1  = (const float*)d_in[2];
    const float* W2  = (const float*)d_in[3];
    const float* b2  = (const float*)d_in[4];
    float* out = (float*)d_out;

    cudaFuncSetAttribute(gemm_bf16, cudaFuncAttributeMaxDynamicSharedMemorySize, SMEM_TOTAL);

    prep_small<<<(BATCH + 255) / 256, 256>>>(b1, W2);
    prep_w1b<<<dim3((KP / 4 + 255) / 256, NP), 256>>>(W1);
    triub<<<BATCH, 256>>>(sim);
    gemm_bf16<<<GRID, 512, SMEM_TOTAL>>>();
    finalize<<<(BATCH + 255) / 256, 256>>>(b2, out);
}

// round 12
// speedup vs baseline: 1.2497x; 1.1138x over previous
#include <cuda_runtime.h>
#include <cuda_bf16.h>
#include <cstdint>

#define MDIM  128
#define FEAT  8256          // MDIM*(MDIM+1)/2
#define HID   1651
#define NP    1664          // HID padded to 13*128
#define KP    8320          // FEAT padded to 130*64
#define BATCH 4096
#define ROWB  (KP * 2)      // global row pitch in bytes

// per-group stage = K64 slice: [A 128rows x 128B | B 128rows x 128B] = 32KB
#define STG_A       16384
#define STG_BYTES   32768
#define NSTG        3
#define GRP_BYTES   (NSTG * STG_BYTES)     // 96 KB per group
#define SMEM_TOTAL  (2 * GRP_BYTES)        // 192 KB
#define KSTG        65                      // K64 stages per group

#define MT 32
#define NT 13
#define NTILES (MT*NT)      // 416
#define GRID   148

#define HSTR 132            // merge-buffer row stride (floats)

// ---------------- device scratch ----------------
__device__ __nv_bfloat16 g_xb [(size_t)BATCH * KP];   // 68.2 MB
__device__ __nv_bfloat16 g_w1b[(size_t)NP    * KP];   // 27.7 MB
__device__ float g_b1[NP];
__device__ float g_w2[NP];
__device__ float g_logits[BATCH];

// ---------------- helpers ----------------
__device__ __forceinline__ uint32_t smem_u32(const void* p) {
    uint32_t a;
    asm("{ .reg .u64 t; cvta.to.shared.u64 t, %1; cvt.u32.u64 %0, t; }" : "=r"(a) : "l"(p));
    return a;
}
#define SWZ128(off) ((off) ^ (((off) >> 3) & 0x70))

__device__ __forceinline__ void ldsm_x4(uint32_t& r0, uint32_t& r1, uint32_t& r2, uint32_t& r3,
                                        uint32_t addr) {
    asm volatile("ldmatrix.sync.aligned.m8n8.x4.shared.b16 {%0,%1,%2,%3}, [%4];"
                 : "=r"(r0), "=r"(r1), "=r"(r2), "=r"(r3) : "r"(addr));
}
__device__ __forceinline__ void mma_bf16(float* c, const uint32_t* a, const uint32_t* b) {
    asm volatile(
        "mma.sync.aligned.m16n8k16.row.col.f32.bf16.bf16.f32 "
        "{%0,%1,%2,%3}, {%4,%5,%6,%7}, {%8,%9}, {%0,%1,%2,%3};"
        : "+f"(c[0]), "+f"(c[1]), "+f"(c[2]), "+f"(c[3])
        : "r"(a[0]), "r"(a[1]), "r"(a[2]), "r"(a[3]), "r"(b[0]), "r"(b[1]));
}

// ---------------- prep kernels ----------------
__global__ void prep_small(const float* __restrict__ b1, const float* __restrict__ w2) {
    int i = blockIdx.x * blockDim.x + threadIdx.x;
    if (i < NP) {
        g_b1[i] = (i < HID) ? b1[i] : 0.0f;
        g_w2[i] = (i < HID) ? w2[i] : 0.0f;
    }
    if (i < BATCH) g_logits[i] = 0.0f;
}

__global__ void prep_w1b(const float* __restrict__ W1) {
    int n  = blockIdx.y;
    int k4 = blockIdx.x * blockDim.x + threadIdx.x;
    if (k4 >= KP / 4) return;
    __nv_bfloat16 o[4] = {__float2bfloat16(0.f), __float2bfloat16(0.f),
                          __float2bfloat16(0.f), __float2bfloat16(0.f)};
    if (n < HID) {
        int k = k4 * 4;
        if (k + 3 < FEAT) {
            float4 v = *(const float4*)&W1[(size_t)n * FEAT + k];
            o[0] = __float2bfloat16(v.x); o[1] = __float2bfloat16(v.y);
            o[2] = __float2bfloat16(v.z); o[3] = __float2bfloat16(v.w);
        } else {
#pragma unroll
            for (int j = 0; j < 4; j++)
                if (k + j < FEAT) o[j] = __float2bfloat16(W1[(size_t)n * FEAT + k + j]);
        }
    }
    *(uint2*)&g_w1b[(size_t)n * KP + k4 * 4] = *(uint2*)o;
}

__global__ __launch_bounds__(256) void triub(const float* __restrict__ sim) {
    int b   = blockIdx.x;
    int tid = threadIdx.x;
    const float* base = sim + (size_t)b * MDIM * MDIM;
    __nv_bfloat16* out = g_xb + (size_t)b * KP;
#pragma unroll
    for (int it = 0; it < 16; ++it) {
        int idx = tid + it * 256;
        int i = idx >> 5;
        int g = idx & 31;
        int j0 = g * 4;
        if (j0 + 3 >= i) {
            float4 v = *(const float4*)&base[i * MDIM + j0];
            int rowoff = i * MDIM - (i * (i - 1)) / 2 - i;
            float vv[4] = {v.x, v.y, v.z, v.w};
#pragma unroll
            for (int l = 0; l < 4; l++) {
                int j = j0 + l;
                if (j >= i) out[rowoff + j] = __float2bfloat16(vv[l]);
            }
        }
    }
    if (tid < KP - FEAT) out[FEAT + tid] = __float2bfloat16(0.f);
}

// ---- bf16 GEMM: CTA 128x128, two decoupled 8-warp K-group pipelines (32x64 tiles) ----
__global__ __launch_bounds__(512, 1) void gemm_bf16() {
    extern __shared__ __align__(1024) uint8_t smem[];
    const uint32_t sbase = smem_u32(smem);
    const int tid  = threadIdx.x;
    const int wid  = tid >> 5;
    const int lid  = tid & 31;
    const int grp  = wid >> 3;          // K-group: 0 = even K64 slices, 1 = odd
    const int gtid = tid & 255;         // thread id within group
    const int barid = 1 + grp;          // named barrier per group
    const int w8  = wid & 7;
    const int wm  = w8 & 3;             // 4 x 32 rows
    const int wn  = w8 >> 2;            // 2 x 64 cols

    const uint32_t gbase = sbase + (uint32_t)grp * GRP_BYTES;

    // hoisted ldmatrix addressing (row-invariant swizzle XOR)
    const int aRow0 = wm * 32 + ((lid >> 3) & 1) * 8 + (lid & 7);
    const int aCol  = (lid >> 4) * 16;
    const uint32_t aXor = (uint32_t)((aRow0 & 7) << 4);
    const int bRow0 = wn * 64 + (lid >> 4) * 8 + (lid & 7);
    const int bCol  = ((lid >> 3) & 1) * 16;
    const uint32_t bXor = (uint32_t)((bRow0 & 7) << 4);

    uint32_t aOff[4], bOff[4];
#pragma unroll
    for (int ks = 0; ks < 4; ks++) {
        aOff[ks] = (uint32_t)(aRow0 * 128) + (((uint32_t)(aCol + ks * 32)) ^ aXor);
        bOff[ks] = STG_A + (uint32_t)(bRow0 * 128) + (((uint32_t)(bCol + ks * 32)) ^ bXor);
    }

    const int qrow = lid >> 2;
    const int qcol = lid & 3;
    float* sh = (float*)smem;           // merge buffer (reuses stage smem between tiles)

    for (int t = blockIdx.x; t < NTILES; t += GRID) {
        const int m0 = (t / NT) * 128;
        const int n0 = (t % NT) * 128;

        float acc[2][8][4];
#pragma unroll
        for (int mi = 0; mi < 2; mi++)
#pragma unroll
            for (int ni = 0; ni < 8; ni++)
#pragma unroll
                for (int c = 0; c < 4; c++) acc[mi][ni][c] = 0.0f;

        // group-private stage load: 256 threads, 32KB, one commit
        auto load_stage = [&](int buf, int kByte) {
            uint32_t st = gbase + buf * STG_BYTES;
#pragma unroll
            for (int it = 0; it < 8; ++it) {
                int idx  = gtid + it * 256;         // 0..2047
                bool isB = idx >= 1024;
                int rel  = idx & 1023;
                int r    = rel >> 3;
                int c    = rel & 7;
                int kb   = kByte + c * 16;
                const uint8_t* src = isB
                    ? (const uint8_t*)g_w1b + (size_t)(n0 + r) * ROWB + kb
                    : (const uint8_t*)g_xb  + (size_t)(m0 + r) * ROWB + kb;
                uint32_t dst = st + (isB ? STG_A : 0) + SWZ128((uint32_t)(r * 128 + c * 16));
                asm volatile("cp.async.cg.shared.global [%0], [%1], 16;"
                             :: "r"(dst), "l"(src) : "memory");
            }
            asm volatile("cp.async.commit_group;" ::: "memory");
        };

        // group g's K64 stage s lives at kByte = (2s+g)*128
        load_stage(0, grp * 128);
        load_stage(1, (2 + grp) * 128);

        for (int s = 0; s < KSTG; ++s) {
            asm volatile("cp.async.wait_group 1;" ::: "memory");
            asm volatile("bar.sync %0, 256;" :: "r"(barid) : "memory");

            if (s + 2 < KSTG) load_stage((s + 2) % NSTG, (2 * (s + 2) + grp) * 128);
            else              asm volatile("cp.async.commit_group;" ::: "memory");

            const uint32_t stg = gbase + (s % NSTG) * STG_BYTES;

#pragma unroll
            for (int ks = 0; ks < 4; ++ks) {
                uint32_t b[8][2];
#pragma unroll
                for (int pp = 0; pp < 4; pp++) {
                    uint32_t r0, r1, r2, r3;
                    ldsm_x4(r0, r1, r2, r3, stg + bOff[ks] + pp * 2048);
                    b[2 * pp][0] = r0; b[2 * pp][1] = r1;
                    b[2 * pp + 1][0] = r2; b[2 * pp + 1][1] = r3;
                }
                uint32_t a[2][4];
                ldsm_x4(a[0][0], a[0][1], a[0][2], a[0][3], stg + aOff[ks]);
                ldsm_x4(a[1][0], a[1][1], a[1][2], a[1][3], stg + aOff[ks] + 2048);
#pragma unroll
                for (int mi = 0; mi < 2; mi++)
#pragma unroll
                    for (int ni = 0; ni < 8; ni++)
                        mma_bf16(acc[mi][ni], a[mi], b[ni]);
            }
        }

        // both groups done computing; stage smem becomes the merge buffer
        __syncthreads();

        if (grp == 1) {
#pragma unroll
            for (int mi = 0; mi < 2; mi++)
#pragma unroll
                for (int ni = 0; ni < 8; ni++) {
                    int r = wm * 32 + mi * 16 + qrow;
                    int cI = wn * 64 + ni * 8 + qcol * 2;
                    *(float2*)&sh[r * HSTR + cI]       = make_float2(acc[mi][ni][0], acc[mi][ni][1]);
                    *(float2*)&sh[(r + 8) * HSTR + cI] = make_float2(acc[mi][ni][2], acc[mi][ni][3]);
                }
        }
        __syncthreads();

        if (grp == 0) {
            // fused epilogue: logits[m] += sum_n relu(acc_merged + b1) * w2
#pragma unroll
            for (int mi = 0; mi < 2; mi++) {
                float r0 = 0.f, r1 = 0.f;
#pragma unroll
                for (int ni = 0; ni < 8; ni++) {
                    int r = wm * 32 + mi * 16 + qrow;
                    int cI = wn * 64 + ni * 8 + qcol * 2;
                    float2 p0 = *(const float2*)&sh[r * HSTR + cI];
                    float2 p1 = *(const float2*)&sh[(r + 8) * HSTR + cI];
                    int n = n0 + cI;
                    float b1a = g_b1[n],     w2a = g_w2[n];
                    float b1b = g_b1[n + 1], w2b = g_w2[n + 1];
                    r0 += fmaxf(acc[mi][ni][0] + p0.x + b1a, 0.f) * w2a
                        + fmaxf(acc[mi][ni][1] + p0.y + b1b, 0.f) * w2b;
                    r1 += fmaxf(acc[mi][ni][2] + p1.x + b1a, 0.f) * w2a
                        + fmaxf(acc[mi][ni][3] + p1.y + b1b, 0.f) * w2b;
                }
                r0 += __shfl_xor_sync(0xffffffffu, r0, 1);
                r0 += __shfl_xor_sync(0xffffffffu, r0, 2);
                r1 += __shfl_xor_sync(0xffffffffu, r1, 1);
                r1 += __shfl_xor_sync(0xffffffffu, r1, 2);
                if (qcol == 0) {
                    int row = m0 + wm * 32 + mi * 16 + qrow;
                    atomicAdd(&g_logits[row],     r0);
                    atomicAdd(&g_logits[row + 8], r1);
                }
            }
        }
        __syncthreads();   // merge buffer free before next tile's prologue
    }
}

// ---------------- finalize ----------------
__global__ void finalize(const float* __restrict__ b2, float* __restrict__ out) {
    int i = blockIdx.x * blockDim.x + threadIdx.x;
    if (i < BATCH) {
        float z = g_logits[i] + b2[0];
        out[i] = 1.0f / (1.0f + expf(-z));
    }
}

// ---------------- launch ----------------
extern "C" void kernel_launch(void* const* d_in, const int* in_sizes, int n_in,
                              void* d_out, int out_size) {
    const float* sim = (const float*)d_in[0];
    const float* W1  = (const float*)d_in[1];
    const float* b1  = (const float*)d_in[2];
    const float* W2  = (const float*)d_in[3];
    const float* b2  = (const float*)d_in[4];
    float* out = (float*)d_out;

    cudaFuncSetAttribute(gemm_bf16, cudaFuncAttributeMaxDynamicSharedMemorySize, SMEM_TOTAL);

    prep_small<<<(BATCH + 255) / 256, 256>>>(b1, W2);
    prep_w1b<<<dim3((KP / 4 + 255) / 256, NP), 256>>>(W1);
    triub<<<BATCH, 256>>>(sim);
    gemm_bf16<<<GRID, 512, SMEM_TOTAL>>>();
    finalize<<<(BATCH + 255) / 256, 256>>>(b2, out);
}

// round 13
// speedup vs baseline: 1.2878x; 1.0305x over previous
#include <cuda_runtime.h>
#include <cuda_bf16.h>
#include <cstdint>

#define MDIM  128
#define FEAT  8256          // MDIM*(MDIM+1)/2
#define HID   1651
#define NP    1664          // HID padded to 13*128
#define KP    8320          // FEAT padded to 130*64
#define BATCH 4096
#define ROWB  (KP * 2)      // global row pitch in bytes (16640)
#define KSTG  130           // K64 stages

// stage = K64 slice: [A 128rows x 128B | B 128rows x 128B] = 32KB
#define STG_A       16384
#define STG_BYTES   32768
#define NSTG        3
#define SMEM_TOTAL  (NSTG * STG_BYTES)     // 96 KB per CTA (2 CTAs/SM)

#define MT 32
#define NT 13
#define NTILES (MT*NT)      // 416
#define GRID   296          // 148 SMs * 2 CTAs

// ---------------- device scratch ----------------
__device__ __nv_bfloat16 g_xb [(size_t)BATCH * KP];   // 68.2 MB
__device__ __nv_bfloat16 g_w1b[(size_t)NP    * KP];   // 27.7 MB
__device__ float g_b1[NP];
__device__ float g_w2[NP];
__device__ float g_logits[BATCH];

// ---------------- helpers ----------------
__device__ __forceinline__ uint32_t smem_u32(const void* p) {
    uint32_t a;
    asm("{ .reg .u64 t; cvta.to.shared.u64 t, %1; cvt.u32.u64 %0, t; }" : "=r"(a) : "l"(p));
    return a;
}
#define SWZ128(off) ((off) ^ (((off) >> 3) & 0x70))

__device__ __forceinline__ void ldsm_x4(uint32_t& r0, uint32_t& r1, uint32_t& r2, uint32_t& r3,
                                        uint32_t addr) {
    asm volatile("ldmatrix.sync.aligned.m8n8.x4.shared.b16 {%0,%1,%2,%3}, [%4];"
                 : "=r"(r0), "=r"(r1), "=r"(r2), "=r"(r3) : "r"(addr));
}
__device__ __forceinline__ void mma_bf16(float* c, const uint32_t* a, const uint32_t* b) {
    asm volatile(
        "mma.sync.aligned.m16n8k16.row.col.f32.bf16.bf16.f32 "
        "{%0,%1,%2,%3}, {%4,%5,%6,%7}, {%8,%9}, {%0,%1,%2,%3};"
        : "+f"(c[0]), "+f"(c[1]), "+f"(c[2]), "+f"(c[3])
        : "r"(a[0]), "r"(a[1]), "r"(a[2]), "r"(a[3]), "r"(b[0]), "r"(b[1]));
}

// ---------------- prep kernels ----------------
__global__ void prep_small(const float* __restrict__ b1, const float* __restrict__ w2) {
    int i = blockIdx.x * blockDim.x + threadIdx.x;
    if (i < NP) {
        g_b1[i] = (i < HID) ? b1[i] : 0.0f;
        g_w2[i] = (i < HID) ? w2[i] : 0.0f;
    }
    if (i < BATCH) g_logits[i] = 0.0f;
}

__global__ void prep_w1b(const float* __restrict__ W1) {
    int n  = blockIdx.y;
    int k4 = blockIdx.x * blockDim.x + threadIdx.x;
    if (k4 >= KP / 4) return;
    __nv_bfloat16 o[4] = {__float2bfloat16(0.f), __float2bfloat16(0.f),
                          __float2bfloat16(0.f), __float2bfloat16(0.f)};
    if (n < HID) {
        int k = k4 * 4;
        if (k + 3 < FEAT) {
            float4 v = *(const float4*)&W1[(size_t)n * FEAT + k];
            o[0] = __float2bfloat16(v.x); o[1] = __float2bfloat16(v.y);
            o[2] = __float2bfloat16(v.z); o[3] = __float2bfloat16(v.w);
        } else {
#pragma unroll
            for (int j = 0; j < 4; j++)
                if (k + j < FEAT) o[j] = __float2bfloat16(W1[(size_t)n * FEAT + k + j]);
        }
    }
    *(uint2*)&g_w1b[(size_t)n * KP + k4 * 4] = *(uint2*)o;
}

__global__ __launch_bounds__(256) void triub(const float* __restrict__ sim) {
    int b   = blockIdx.x;
    int tid = threadIdx.x;
    const float* base = sim + (size_t)b * MDIM * MDIM;
    __nv_bfloat16* out = g_xb + (size_t)b * KP;
#pragma unroll
    for (int it = 0; it < 16; ++it) {
        int idx = tid + it * 256;
        int i = idx >> 5;
        int g = idx & 31;
        int j0 = g * 4;
        if (j0 + 3 >= i) {
            float4 v = *(const float4*)&base[i * MDIM + j0];
            int rowoff = i * MDIM - (i * (i - 1)) / 2 - i;
            float vv[4] = {v.x, v.y, v.z, v.w};
#pragma unroll
            for (int l = 0; l < 4; l++) {
                int j = j0 + l;
                if (j >= i) out[rowoff + j] = __float2bfloat16(vv[l]);
            }
        }
    }
    if (tid < KP - FEAT) out[FEAT + tid] = __float2bfloat16(0.f);
}

// ---- bf16 GEMM: 2 CTAs/SM, CTA 128x128 with 8 warps (32x64), full-K pipelines ----
__global__ __launch_bounds__(256, 2) void gemm_bf16() {
    extern __shared__ __align__(1024) uint8_t smem[];
    const uint32_t sbase = smem_u32(smem);
    const int tid = threadIdx.x;
    const int wid = tid >> 5;
    const int lid = tid & 31;
    const int wm  = wid & 3;            // 4 x 32 rows
    const int wn  = wid >> 2;           // 2 x 64 cols

    // consumer: hoisted ldmatrix addressing (row-invariant swizzle XOR)
    const int aRow0 = wm * 32 + ((lid >> 3) & 1) * 8 + (lid & 7);
    const int aCol  = (lid >> 4) * 16;
    const uint32_t aXor = (uint32_t)((aRow0 & 7) << 4);
    const int bRow0 = wn * 64 + (lid >> 4) * 8 + (lid & 7);
    const int bCol  = ((lid >> 3) & 1) * 16;
    const uint32_t bXor = (uint32_t)((bRow0 & 7) << 4);

    uint32_t aOff[4], bOff[4];
#pragma unroll
    for (int ks = 0; ks < 4; ks++) {
        aOff[ks] = (uint32_t)(aRow0 * 128) + (((uint32_t)(aCol + ks * 32)) ^ aXor);
        bOff[ks] = STG_A + (uint32_t)(bRow0 * 128) + (((uint32_t)(bCol + ks * 32)) ^ bXor);
    }

    // producer: thread owns rows (pr + 32*it), col chunk pc, for both A and B
    const int pr = tid >> 3;            // 0..31
    const int pc = tid & 7;
    const uint32_t dstSw = SWZ128((uint32_t)(pr * 128 + pc * 16));  // +4096 per it (row&7 inv.)

    const int qrow = lid >> 2;
    const int qcol = lid & 3;

    for (int t = blockIdx.x; t < NTILES; t += GRID) {
        const int m0 = (t / NT) * 128;
        const int n0 = (t % NT) * 128;

        const uint8_t* aSrc = (const uint8_t*)g_xb  + (size_t)(m0 + pr) * ROWB + pc * 16;
        const uint8_t* bSrc = (const uint8_t*)g_w1b + (size_t)(n0 + pr) * ROWB + pc * 16;

        float acc[2][8][4];
#pragma unroll
        for (int mi = 0; mi < 2; mi++)
#pragma unroll
            for (int ni = 0; ni < 8; ni++)
#pragma unroll
                for (int c = 0; c < 4; c++) acc[mi][ni][c] = 0.0f;

        // stage load: 4 A + 4 B chunks per thread, pointer-relative, then advance
        auto load_stage = [&](uint32_t stgOff) {
            uint32_t d = sbase + stgOff + dstSw;
#pragma unroll
            for (int it = 0; it < 4; ++it) {
                asm volatile("cp.async.cg.shared.global [%0], [%1], 16;"
                             :: "r"(d + it * 4096),
                                "l"(aSrc + (size_t)it * 32 * ROWB) : "memory");
                asm volatile("cp.async.cg.shared.global [%0], [%1], 16;"
                             :: "r"(d + STG_A + it * 4096),
                                "l"(bSrc + (size_t)it * 32 * ROWB) : "memory");
            }
            asm volatile("cp.async.commit_group;" ::: "memory");
            aSrc += 128; bSrc += 128;
        };

        load_stage(0);
        load_stage(STG_BYTES);

        uint32_t cOff = 0;                  // compute buffer offset
        uint32_t lOff = 2 * STG_BYTES;      // next load buffer offset

        for (int s = 0; s < KSTG; ++s) {
            asm volatile("cp.async.wait_group 1;" ::: "memory");
            __syncthreads();

            if (s + 2 < KSTG) {
                load_stage(lOff);
                lOff = (lOff == 2 * STG_BYTES) ? 0u : lOff + STG_BYTES;
            } else {
                asm volatile("cp.async.commit_group;" ::: "memory");
            }

            const uint32_t stg = sbase + cOff;
            cOff = (cOff == 2 * STG_BYTES) ? 0u : cOff + STG_BYTES;

#pragma unroll
            for (int ks = 0; ks < 4; ++ks) {
                const uint32_t bb = stg + bOff[ks];
                uint32_t b[8][2];
#pragma unroll
                for (int pp = 0; pp < 4; pp++) {
                    uint32_t r0, r1, r2, r3;
                    ldsm_x4(r0, r1, r2, r3, bb + pp * 2048);
                    b[2 * pp][0] = r0; b[2 * pp][1] = r1;
                    b[2 * pp + 1][0] = r2; b[2 * pp + 1][1] = r3;
                }
                const uint32_t aa = stg + aOff[ks];
                uint32_t a[2][4];
                ldsm_x4(a[0][0], a[0][1], a[0][2], a[0][3], aa);
                ldsm_x4(a[1][0], a[1][1], a[1][2], a[1][3], aa + 2048);
#pragma unroll
                for (int mi = 0; mi < 2; mi++)
#pragma unroll
                    for (int ni = 0; ni < 8; ni++)
                        mma_bf16(acc[mi][ni], a[mi], b[ni]);
            }
        }
        __syncthreads();   // all LDSM done before next tile's prologue overwrites buf 0

        // -------- fused epilogue: logits[m] += sum_n relu(acc + b1) * w2 --------
#pragma unroll
        for (int mi = 0; mi < 2; mi++) {
            float r0 = 0.f, r1 = 0.f;
#pragma unroll
            for (int ni = 0; ni < 8; ni++) {
                int n = n0 + wn * 64 + ni * 8 + qcol * 2;
                float b1a = g_b1[n],     w2a = g_w2[n];
                float b1b = g_b1[n + 1], w2b = g_w2[n + 1];
                r0 += fmaxf(acc[mi][ni][0] + b1a, 0.f) * w2a
                    + fmaxf(acc[mi][ni][1] + b1b, 0.f) * w2b;
                r1 += fmaxf(acc[mi][ni][2] + b1a, 0.f) * w2a
                    + fmaxf(acc[mi][ni][3] + b1b, 0.f) * w2b;
            }
            r0 += __shfl_xor_sync(0xffffffffu, r0, 1);
            r0 += __shfl_xor_sync(0xffffffffu, r0, 2);
            r1 += __shfl_xor_sync(0xffffffffu, r1, 1);
            r1 += __shfl_xor_sync(0xffffffffu, r1, 2);
            if (qcol == 0) {
                int row = m0 + wm * 32 + mi * 16 + qrow;
                atomicAdd(&g_logits[row],     r0);
                atomicAdd(&g_logits[row + 8], r1);
            }
        }
    }
}

// ---------------- finalize ----------------
__global__ void finalize(const float* __restrict__ b2, float* __restrict__ out) {
    int i = blockIdx.x * blockDim.x + threadIdx.x;
    if (i < BATCH) {
        float z = g_logits[i] + b2[0];
        out[i] = 1.0f / (1.0f + expf(-z));
    }
}

// ---------------- launch ----------------
extern "C" void kernel_launch(void* const* d_in, const int* in_sizes, int n_in,
                              void* d_out, int out_size) {
    const float* sim = (const float*)d_in[0];
    const float* W1  = (const float*)d_in[1];
    const float* b1  = (const float*)d_in[2];
    const float* W2  = (const float*)d_in[3];
    const float* b2  = (const float*)d_in[4];
    float* out = (float*)d_out;

    cudaFuncSetAttribute(gemm_bf16, cudaFuncAttributeMaxDynamicSharedMemorySize, SMEM_TOTAL);

    prep_small<<<(BATCH + 255) / 256, 256>>>(b1, W2);
    prep_w1b<<<dim3((KP / 4 + 255) / 256, NP), 256>>>(W1);
    triub<<<BATCH, 256>>>(sim);
    gemm_bf16<<<GRID, 256, SMEM_TOTAL>>>();
    finalize<<<(BATCH + 255) / 256, 256>>>(b2, out);
}